// round 13
// baseline (speedup 1.0000x reference)
#include <cuda_runtime.h>
#include <cuda_fp16.h>
#include <math.h>
#include <float.h>
#include <stdint.h>

#define L_SEQ 2048
#define NB 2
#define DM 1024
#define NH 16
#define DHEAD 64
#define SPAN_W 128
#define MROWS (L_SEQ * NB)          // 4096
#define HB (NH * NB)                // 32

// ---------------- static scratch (no allocations allowed) ----------------
__device__ float g_fc[MROWS * DM];               // FC output (pre-LN)
__device__ float g_rowl[HB * L_SEQ];             // softmax row sum

// fp16 operands (all single-rounded now)
__device__ __half g_inhi[3][MROWS * DM];         // q/k/v inputs
__device__ __half g_wth[4][DM * DM];             // W^T [n][k]
__device__ __half g_aohi[MROWS * DM];            // attnout
// projected Q (x0.125) / K, head-major [hb][l][dk]
__device__ __half g_qh[HB * L_SEQ * DHEAD];
__device__ __half g_kh[HB * L_SEQ * DHEAD];
// projected V transposed [hb][dv][l]
__device__ __half g_vth[HB * DHEAD * L_SEQ];

// ---------------- helpers ----------------
__device__ __forceinline__ uint32_t smem_u32(const void* p) {
    uint32_t a;
    asm("{ .reg .u64 t; cvta.to.shared.u64 t, %1; cvt.u32.u64 %0, t; }"
        : "=r"(a) : "l"(p));
    return a;
}
__device__ __forceinline__ void ldsm4(uint32_t (&r)[4], uint32_t addr) {
    asm volatile("ldmatrix.sync.aligned.m8n8.x4.shared.b16 {%0,%1,%2,%3}, [%4];"
                 : "=r"(r[0]), "=r"(r[1]), "=r"(r[2]), "=r"(r[3]) : "r"(addr));
}
__device__ __forceinline__ void mma_f16(float (&d)[4], const uint32_t (&a)[4],
                                        uint32_t b0, uint32_t b1) {
    asm volatile(
        "mma.sync.aligned.m16n8k16.row.col.f32.f16.f16.f32 "
        "{%0,%1,%2,%3}, {%4,%5,%6,%7}, {%8,%9}, {%0,%1,%2,%3};"
        : "+f"(d[0]), "+f"(d[1]), "+f"(d[2]), "+f"(d[3])
        : "r"(a[0]), "r"(a[1]), "r"(a[2]), "r"(a[3]), "r"(b0), "r"(b1));
}
#define CPA16(saddr, gptr) \
    asm volatile("cp.async.cg.shared.global [%0], [%1], 16;" \
                 :: "r"(saddr), "l"(__cvta_generic_to_global(gptr)) : "memory")
#define CPA_COMMIT() asm volatile("cp.async.commit_group;" ::: "memory")
#define CPA_WAIT0()  asm volatile("cp.async.wait_group 0;" ::: "memory")

// fast exp on FMA pipe, ~1e-7 rel (|x| < 80)
__device__ __forceinline__ float fexp(float x) {
    x = fmaxf(x, -80.f);
    float t = fmaf(x, 1.4426950408889634f, 12582912.f);
    float n = t - 12582912.f;
    float f = fmaf(n, -0.693145751953125f, x);
    f = fmaf(n, -1.428606765330187e-06f, f);
    float p = 1.3888889e-3f;
    p = fmaf(p, f, 8.3333338e-3f);
    p = fmaf(p, f, 4.1666668e-2f);
    p = fmaf(p, f, 1.6666667e-1f);
    p = fmaf(p, f, 5.0e-1f);
    p = fmaf(p, f, 1.0f);
    p = fmaf(p, f, 1.0f);
    int i = (int)n;
    return __int_as_float(__float_as_int(p) + (i << 23));
}
__device__ __forceinline__ uint32_t packh2(float a, float b) {
    __half2 t = __floats2half2_rn(a, b);
    return *reinterpret_cast<uint32_t*>(&t);
}

// ======================== converter kernels ==============================
__global__ void __launch_bounds__(256)
conv_in_kernel(const float* __restrict__ q, const float* __restrict__ k,
               const float* __restrict__ v)
{
    const int z = blockIdx.y;
    const float* src = (z == 0) ? q : (z == 1) ? k : v;
    __half* dhi = g_inhi[z];
    size_t base = ((size_t)blockIdx.x * 256 + threadIdx.x) * 8;
    float4 a = *(const float4*)(src + base);
    float4 b = *(const float4*)(src + base + 4);
    __half hi[8];
    float xs[8] = {a.x, a.y, a.z, a.w, b.x, b.y, b.z, b.w};
#pragma unroll
    for (int i = 0; i < 8; i++) hi[i] = __float2half_rn(xs[i]);
    *(uint4*)(dhi + base) = *(uint4*)hi;
}

__global__ void __launch_bounds__(256)
conv_w_kernel(const float* __restrict__ Wq, const float* __restrict__ Wk,
              const float* __restrict__ Wv, const float* __restrict__ Wfc)
{
    __shared__ float tile[32][33];
    const int z = blockIdx.z;
    const float* W = (z == 0) ? Wq : (z == 1) ? Wk : (z == 2) ? Wv : Wfc;
    __half* dh = g_wth[z];
    const int n0 = blockIdx.x * 32, k0 = blockIdx.y * 32;
    const int c = threadIdx.x & 31, r0 = (threadIdx.x >> 5) * 4;
#pragma unroll
    for (int rr = 0; rr < 4; rr++)
        tile[r0 + rr][c] = W[(size_t)(k0 + r0 + rr) * DM + n0 + c];
    __syncthreads();
#pragma unroll
    for (int rr = 0; rr < 4; rr++) {
        int n = n0 + r0 + rr;
        dh[(size_t)n * DM + k0 + c] = __float2half_rn(tile[c][r0 + rr]);
    }
}

// ======================== fp16 HMMA GEMM (cp.async, 1-term) ==============
#define TSX 40
#define TILE_B (128 * TSX * 2)
#define GEMM_SMEM_BYTES (2 * 2 * TILE_B)   // 40960

__global__ void __launch_bounds__(256, 2)
mma_gemm_kernel(const float* __restrict__ bq, const float* __restrict__ bk,
                const float* __restrict__ bv, const float* __restrict__ bfc,
                int is_fc)
{
    extern __shared__ char dyn[];
    const uint32_t sb = smem_u32(dyn);
    const int tid = threadIdx.x, wid = tid >> 5, lane = tid & 31;
    const int m0 = blockIdx.x * 128, n0 = blockIdx.y * 128;
    const int z = blockIdx.z;

    const __half *Ah, *Bh;
    const float* bias;
    if (is_fc) {
        Ah = g_aohi; Bh = g_wth[3]; bias = bfc;
    } else {
        Ah = g_inhi[z]; Bh = g_wth[z];
        bias = (z == 0) ? bq : (z == 1) ? bk : bv;
    }
    const __half* srcs[2] = { Ah + (size_t)m0 * DM, Bh + (size_t)n0 * DM };

    const int wm = (wid & 3) * 32;
    const int wn = (wid >> 2) * 64;

    float acc[2][8][4];
#pragma unroll
    for (int ms = 0; ms < 2; ms++)
#pragma unroll
        for (int ns = 0; ns < 8; ns++)
#pragma unroll
            for (int c = 0; c < 4; c++) acc[ms][ns][c] = 0.f;

    const int r_ld = tid >> 2;
    const int c_ld = (tid & 3) * 8;

    auto issue_tile = [&](int buf, int k0) {
#pragma unroll
        for (int t = 0; t < 2; t++)
#pragma unroll
            for (int u = 0; u < 2; u++) {
                uint32_t sa = sb + buf * (2 * TILE_B) + t * TILE_B +
                              ((r_ld + u * 64) * TSX + c_ld) * 2;
                CPA16(sa, srcs[t] + (size_t)(r_ld + u * 64) * DM + k0 + c_ld);
            }
        CPA_COMMIT();
    };

    issue_tile(0, 0);
    CPA_WAIT0();
    __syncthreads();

    const int rowA = wm + (lane & 15);
    const int colA = (lane >> 4) << 3;
    const int rowB = wn + (lane & 7) + ((lane >> 4) << 3);
    const int colB = ((lane >> 3) & 1) << 3;

    for (int step = 0; step < 32; step++) {
        const int buf = step & 1;
        const uint32_t base = sb + buf * (2 * TILE_B);
        const int has_next = (step + 1 < 32);
        if (has_next) issue_tile(buf ^ 1, (step + 1) * 32);

#pragma unroll
        for (int kh = 0; kh < 32; kh += 16) {
            uint32_t ah[2][4];
#pragma unroll
            for (int ms = 0; ms < 2; ms++) {
                uint32_t off = ((rowA + ms * 16) * TSX + kh + colA) * 2;
                ldsm4(ah[ms], base + off);
            }
            uint32_t bh[8][2];
#pragma unroll
            for (int np = 0; np < 4; np++) {
                uint32_t off = ((rowB + np * 16) * TSX + kh + colB) * 2;
                uint32_t t4[4];
                ldsm4(t4, base + TILE_B + off);
                bh[2 * np][0] = t4[0]; bh[2 * np][1] = t4[1];
                bh[2 * np + 1][0] = t4[2]; bh[2 * np + 1][1] = t4[3];
            }
#pragma unroll
            for (int ms = 0; ms < 2; ms++)
#pragma unroll
                for (int ns = 0; ns < 8; ns++)
                    mma_f16(acc[ms][ns], ah[ms], bh[ns][0], bh[ns][1]);
        }
        if (has_next) {
            CPA_WAIT0();
            __syncthreads();
        }
    }

    const int qrow = lane >> 2;
    const int qcol = (lane & 3) * 2;
    const float scale = (!is_fc && z == 0) ? 0.125f : 1.0f;
#pragma unroll
    for (int ms = 0; ms < 2; ms++) {
#pragma unroll
        for (int ns = 0; ns < 8; ns++) {
            const int ncol = n0 + wn + ns * 8 + qcol;
            const float b0 = bias[ncol], b1 = bias[ncol + 1];
#pragma unroll
            for (int half = 0; half < 2; half++) {
                const int m = m0 + wm + ms * 16 + qrow + half * 8;
                float x0 = (acc[ms][ns][2 * half] + b0) * scale;
                float x1 = (acc[ms][ns][2 * half + 1] + b1) * scale;
                if (is_fc) {
                    *(float2*)(g_fc + (size_t)m * DM + ncol) = make_float2(x0, x1);
                } else {
                    const int l = m >> 1, bb = m & 1;
                    const int h = ncol >> 6, dkb = ncol & 63;
                    if (z < 2) {
                        size_t idx = ((size_t)(h * NB + bb) * L_SEQ + l) * DHEAD + dkb;
                        __half* dst = (z == 0) ? g_qh : g_kh;
                        *(uint32_t*)(dst + idx) = packh2(x0, x1);
                    } else {
                        size_t base2 = ((size_t)(h * NB + bb) * DHEAD + dkb) * L_SEQ + l;
                        g_vth[base2] = __float2half_rn(x0);
                        g_vth[base2 + L_SEQ] = __float2half_rn(x1);
                    }
                }
            }
        }
    }
}

// =========================================================================
// fp16 HMMA banded attention, single pass, 1-term throughout, P in regs.
// Writes unnormalized p to gmem; row sums to g_rowl.
// =========================================================================
#define QKS 72           // Q/K smem row stride (halves)
#define VTS 136          // Vt smem row stride
#define OFF_QH 0
#define OFF_KH 18432
#define OFF_VH 36864
#define ATTN_SMEM_BYTES (36864 + 64 * VTS * 2)   // 54272

__global__ void __launch_bounds__(256, 2)
attn_kernel(float* __restrict__ attn_raw)
{
    extern __shared__ char dyn[];
    const uint32_t sb = smem_u32(dyn);
    const int tid = threadIdx.x, wid = tid >> 5, lane = tid & 31;
    const int w16 = wid * 16;
    const int i0 = blockIdx.x * 128;
    const int hb = blockIdx.y;

    const __half* Qh = g_qh + (size_t)hb * L_SEQ * DHEAD;
    const __half* Kh = g_kh + (size_t)hb * L_SEQ * DHEAD;
    const __half* Vh = g_vth + (size_t)hb * DHEAD * L_SEQ;
    float* rawbase = attn_raw + (size_t)hb * L_SEQ * L_SEQ;

    // load Q tile (persistent)
    {
        const __half* src = Qh + (size_t)i0 * DHEAD;
#pragma unroll
        for (int u = 0; u < 4; u++) {
            int idx = tid + u * 256;
            int r = idx >> 3, c = idx & 7;
            *(uint4*)(dyn + OFF_QH + (r * QKS + c * 8) * 2) =
                *(const uint4*)(src + (size_t)r * DHEAD + c * 8);
        }
    }

    const int ir0 = i0 + w16 + (lane >> 2);
    const int ir1 = ir0 + 8;
    const int jco = 2 * (lane & 3);

    const uint32_t qoff = ((w16 + (lane & 15)) * QKS + ((lane >> 4) << 3)) * 2;
    const uint32_t brow = (lane & 7) + ((lane >> 4) << 3);
    const uint32_t bcol = ((lane >> 3) & 1) << 3;

    float O[8][4];
#pragma unroll
    for (int n = 0; n < 8; n++)
#pragma unroll
        for (int e = 0; e < 4; e++) O[n][e] = 0.f;
    float sum0 = 0.f, sum1 = 0.f;

    for (int cch = 0; cch < 3; cch++) {
        int j0 = i0 + (cch - 1) * 128;
        if (j0 < 0 || j0 >= L_SEQ) continue;
        __syncthreads();     // prev chunk K/V fully consumed
        {
#pragma unroll
            for (int u = 0; u < 4; u++) {
                int idx = tid + u * 256;
                int r = idx >> 3, c = idx & 7;
                *(uint4*)(dyn + OFF_KH + (r * QKS + c * 8) * 2) =
                    *(const uint4*)(Kh + (size_t)(j0 + r) * DHEAD + c * 8);
            }
#pragma unroll
            for (int u = 0; u < 4; u++) {
                int idx = tid + u * 256;
                int r = idx >> 4, c = idx & 15;
                *(uint4*)(dyn + OFF_VH + (r * VTS + c * 8) * 2) =
                    *(const uint4*)(Vh + (size_t)r * L_SEQ + j0 + c * 8);
            }
        }
        __syncthreads();

#pragma unroll
        for (int half = 0; half < 2; half++) {
            // ---- S = Q K^T for 64 j-cols (1-term) ----
            float Sv[8][4];
#pragma unroll
            for (int n = 0; n < 8; n++)
#pragma unroll
                for (int e = 0; e < 4; e++) Sv[n][e] = 0.f;
#pragma unroll
            for (int ks = 0; ks < 4; ks++) {
                uint32_t ah[4];
                ldsm4(ah, sb + OFF_QH + qoff + ks * 32);
#pragma unroll
                for (int n2 = 0; n2 < 4; n2++) {
                    uint32_t off = ((half * 64 + n2 * 16 + brow) * QKS + ks * 16 + bcol) * 2;
                    uint32_t kh4[4];
                    ldsm4(kh4, sb + OFF_KH + off);
                    mma_f16(Sv[2 * n2], ah, kh4[0], kh4[1]);
                    mma_f16(Sv[2 * n2 + 1], ah, kh4[2], kh4[3]);
                }
            }

            // ---- mask + exp (m=0) + gmem p + row sums ----
#pragma unroll
            for (int n = 0; n < 8; n++) {
                int j = j0 + half * 64 + n * 8 + jco;
                int d0 = ir0 - j, d1 = ir1 - j;
                float p00 = (d0 >= -SPAN_W && d0 <= SPAN_W) ? fexp(Sv[n][0]) : 0.f;
                float p01 = (d0 - 1 >= -SPAN_W && d0 - 1 <= SPAN_W) ? fexp(Sv[n][1]) : 0.f;
                float p10 = (d1 >= -SPAN_W && d1 <= SPAN_W) ? fexp(Sv[n][2]) : 0.f;
                float p11 = (d1 - 1 >= -SPAN_W && d1 - 1 <= SPAN_W) ? fexp(Sv[n][3]) : 0.f;
                sum0 += p00 + p01;
                sum1 += p10 + p11;
                *(float2*)(rawbase + (size_t)ir0 * L_SEQ + j) = make_float2(p00, p01);
                *(float2*)(rawbase + (size_t)ir1 * L_SEQ + j) = make_float2(p10, p11);
                Sv[n][0] = p00; Sv[n][1] = p01; Sv[n][2] = p10; Sv[n][3] = p11;
            }

            // ---- O += P V (single-term P, A-fragments from registers) ----
#pragma unroll
            for (int t = 0; t < 4; t++) {
                uint32_t af[4];
                af[0] = packh2(Sv[2 * t][0], Sv[2 * t][1]);
                af[1] = packh2(Sv[2 * t][2], Sv[2 * t][3]);
                af[2] = packh2(Sv[2 * t + 1][0], Sv[2 * t + 1][1]);
                af[3] = packh2(Sv[2 * t + 1][2], Sv[2 * t + 1][3]);
#pragma unroll
                for (int n2 = 0; n2 < 4; n2++) {
                    uint32_t off = ((n2 * 16 + brow) * VTS + half * 64 + t * 16 + bcol) * 2;
                    uint32_t vh4[4];
                    ldsm4(vh4, sb + OFF_VH + off);
                    mma_f16(O[2 * n2], af, vh4[0], vh4[1]);
                    mma_f16(O[2 * n2 + 1], af, vh4[2], vh4[3]);
                }
            }
        }
    }

    sum0 += __shfl_xor_sync(0xffffffffu, sum0, 1);
    sum0 += __shfl_xor_sync(0xffffffffu, sum0, 2);
    sum1 += __shfl_xor_sync(0xffffffffu, sum1, 1);
    sum1 += __shfl_xor_sync(0xffffffffu, sum1, 2);
    const float inv0 = 1.f / sum0;
    const float inv1 = 1.f / sum1;
    if ((lane & 3) == 0) {
        g_rowl[hb * L_SEQ + ir0] = sum0;
        g_rowl[hb * L_SEQ + ir1] = sum1;
    }

    // epilogue: attnout single fp16  [l b][h dv]
    const int h = hb >> 1, bb = hb & 1;
#pragma unroll
    for (int n = 0; n < 8; n++) {
        int dv = n * 8 + jco;
        size_t i0x = ((size_t)ir0 * NB + bb) * DM + h * DHEAD + dv;
        size_t i1x = ((size_t)ir1 * NB + bb) * DM + h * DHEAD + dv;
        *(uint32_t*)(g_aohi + i0x) = packh2(O[n][0] * inv0, O[n][1] * inv0);
        *(uint32_t*)(g_aohi + i1x) = packh2(O[n][2] * inv1, O[n][3] * inv1);
    }
}

// =========================================================================
// Normalize: per-8-group band test; only overlapping groups load.
// =========================================================================
__global__ void __launch_bounds__(256)
attn_norm_kernel(float* __restrict__ attn)
{
    const int row = blockIdx.x;
    const int i = row & (L_SEQ - 1);
    float* p = attn + (size_t)row * L_SEQ;
    const int j0 = threadIdx.x * 8;
    const bool overlap = (j0 + 7 >= i - SPAN_W) && (j0 <= i + SPAN_W);
    if (!overlap) {
        float4 zz = make_float4(0.f, 0.f, 0.f, 0.f);
        *(float4*)&p[j0] = zz;
        *(float4*)&p[j0 + 4] = zz;
        return;
    }
    const float inv = 1.f / g_rowl[row];
    float4 a = *(const float4*)&p[j0];
    float4 b = *(const float4*)&p[j0 + 4];
    float out[8] = {a.x, a.y, a.z, a.w, b.x, b.y, b.z, b.w};
#pragma unroll
    for (int u = 0; u < 8; u++) {
        int d = i - (j0 + u);
        out[u] = (d >= -SPAN_W && d <= SPAN_W) ? out[u] * inv : 0.f;
    }
    *(float4*)&p[j0]     = make_float4(out[0], out[1], out[2], out[3]);
    *(float4*)&p[j0 + 4] = make_float4(out[4], out[5], out[6], out[7]);
}

// =========================================================================
// Residual + LayerNorm.
// =========================================================================
__global__ void __launch_bounds__(256)
ln_kernel(const float* __restrict__ query, const float* __restrict__ gamma,
          const float* __restrict__ beta, float* __restrict__ y)
{
    __shared__ float red[16];
    const int row = blockIdx.x;
    const int t = threadIdx.x;

    float4 f = *(const float4*)&g_fc[(size_t)row * DM + t * 4];
    float4 q = *(const float4*)&query[(size_t)row * DM + t * 4];
    float v0 = f.x + q.x, v1 = f.y + q.y, v2 = f.z + q.z, v3 = f.w + q.w;

    float s = v0 + v1 + v2 + v3;
    float s2 = v0 * v0 + v1 * v1 + v2 * v2 + v3 * v3;
#pragma unroll
    for (int off = 16; off > 0; off >>= 1) {
        s  += __shfl_xor_sync(0xffffffffu, s, off);
        s2 += __shfl_xor_sync(0xffffffffu, s2, off);
    }
    const int warp = t >> 5, lane = t & 31;
    if (lane == 0) { red[warp] = s; red[warp + 8] = s2; }
    __syncthreads();
    if (t < 32) {
        float a  = (lane < 8) ? red[lane] : 0.f;
        float b2 = (lane < 8) ? red[lane + 8] : 0.f;
#pragma unroll
        for (int off = 4; off > 0; off >>= 1) {
            a  += __shfl_xor_sync(0xffffffffu, a, off);
            b2 += __shfl_xor_sync(0xffffffffu, b2, off);
        }
        if (lane == 0) { red[0] = a; red[1] = b2; }
    }
    __syncthreads();
    const float mean = red[0] * (1.f / DM);
    const float var  = red[1] * (1.f / DM) - mean * mean;
    const float rstd = rsqrtf(var + 1e-5f);

    float4 g  = *(const float4*)&gamma[t * 4];
    float4 be = *(const float4*)&beta[t * 4];
    float4 o;
    o.x = (v0 - mean) * rstd * g.x + be.x;
    o.y = (v1 - mean) * rstd * g.y + be.y;
    o.z = (v2 - mean) * rstd * g.z + be.z;
    o.w = (v3 - mean) * rstd * g.w + be.w;
    *(float4*)&y[(size_t)row * DM + t * 4] = o;
}

// =========================================================================
extern "C" void kernel_launch(void* const* d_in, const int* in_sizes, int n_in,
                              void* d_out, int out_size)
{
    const float* query = (const float*)d_in[0];
    const float* key   = (const float*)d_in[1];
    const float* value = (const float*)d_in[2];
    const float* Wq    = (const float*)d_in[3];
    const float* bq    = (const float*)d_in[4];
    const float* Wk    = (const float*)d_in[5];
    const float* bk    = (const float*)d_in[6];
    const float* Wv    = (const float*)d_in[7];
    const float* bv    = (const float*)d_in[8];
    const float* Wfc   = (const float*)d_in[9];
    const float* bfc   = (const float*)d_in[10];
    const float* gamma = (const float*)d_in[11];
    const float* beta  = (const float*)d_in[12];

    float* y_out = (float*)d_out;
    float* attn_out = y_out + (size_t)L_SEQ * NB * DM;

    cudaFuncSetAttribute(attn_kernel,
                         cudaFuncAttributeMaxDynamicSharedMemorySize,
                         ATTN_SMEM_BYTES);
    cudaFuncSetAttribute(mma_gemm_kernel,
                         cudaFuncAttributeMaxDynamicSharedMemorySize,
                         GEMM_SMEM_BYTES);

    conv_w_kernel<<<dim3(DM / 32, DM / 32, 4), 256>>>(Wq, Wk, Wv, Wfc);
    conv_in_kernel<<<dim3(MROWS * DM / 2048, 3), 256>>>(query, key, value);

    mma_gemm_kernel<<<dim3(MROWS / 128, DM / 128, 3), 256, GEMM_SMEM_BYTES>>>(
        bq, bk, bv, bfc, 0);

    attn_kernel<<<dim3(L_SEQ / 128, HB), 256, ATTN_SMEM_BYTES>>>(attn_out);

    mma_gemm_kernel<<<dim3(MROWS / 128, DM / 128, 1), 256, GEMM_SMEM_BYTES>>>(
        bq, bk, bv, bfc, 1);

    ln_kernel<<<MROWS, 256>>>(query, gamma, beta, y_out);

    attn_norm_kernel<<<HB * L_SEQ, 256>>>(attn_out);
}

// round 14
// speedup vs baseline: 1.4546x; 1.4546x over previous
#include <cuda_runtime.h>
#include <cuda_fp16.h>
#include <math.h>
#include <float.h>
#include <stdint.h>

#define L_SEQ 2048
#define NB 2
#define DM 1024
#define NH 16
#define DHEAD 64
#define SPAN_W 128
#define MROWS (L_SEQ * NB)          // 4096
#define HB (NH * NB)                // 32

// ---------------- static scratch (no allocations allowed) ----------------
__device__ float g_fc[MROWS * DM];               // FC output (pre-LN)
__device__ float g_rowl[HB * L_SEQ];             // softmax row sum

// fp16 operands (activations/weights single-rounded)
__device__ __half g_inhi[3][MROWS * DM];         // q/k/v inputs
__device__ __half g_wth[4][DM * DM];             // W^T [n][k]
__device__ __half g_aohi[MROWS * DM];            // attnout
// projected Q (x0.125) hi/lo (exact split) + K single, head-major [hb][l][dk]
__device__ __half g_qh[HB * L_SEQ * DHEAD];
__device__ __half g_ql[HB * L_SEQ * DHEAD];
__device__ __half g_kh[HB * L_SEQ * DHEAD];
// projected V transposed [hb][dv][l]
__device__ __half g_vth[HB * DHEAD * L_SEQ];

// ---------------- helpers ----------------
__device__ __forceinline__ uint32_t smem_u32(const void* p) {
    uint32_t a;
    asm("{ .reg .u64 t; cvta.to.shared.u64 t, %1; cvt.u32.u64 %0, t; }"
        : "=r"(a) : "l"(p));
    return a;
}
__device__ __forceinline__ void ldsm4(uint32_t (&r)[4], uint32_t addr) {
    asm volatile("ldmatrix.sync.aligned.m8n8.x4.shared.b16 {%0,%1,%2,%3}, [%4];"
                 : "=r"(r[0]), "=r"(r[1]), "=r"(r[2]), "=r"(r[3]) : "r"(addr));
}
__device__ __forceinline__ void mma_f16(float (&d)[4], const uint32_t (&a)[4],
                                        uint32_t b0, uint32_t b1) {
    asm volatile(
        "mma.sync.aligned.m16n8k16.row.col.f32.f16.f16.f32 "
        "{%0,%1,%2,%3}, {%4,%5,%6,%7}, {%8,%9}, {%0,%1,%2,%3};"
        : "+f"(d[0]), "+f"(d[1]), "+f"(d[2]), "+f"(d[3])
        : "r"(a[0]), "r"(a[1]), "r"(a[2]), "r"(a[3]), "r"(b0), "r"(b1));
}
#define CPA16(saddr, gptr) \
    asm volatile("cp.async.cg.shared.global [%0], [%1], 16;" \
                 :: "r"(saddr), "l"(__cvta_generic_to_global(gptr)) : "memory")
#define CPA_COMMIT() asm volatile("cp.async.commit_group;" ::: "memory")
#define CPA_WAIT0()  asm volatile("cp.async.wait_group 0;" ::: "memory")

// fast exp on FMA pipe, ~1e-7 rel (|x| < 80)
__device__ __forceinline__ float fexp(float x) {
    x = fmaxf(x, -80.f);
    float t = fmaf(x, 1.4426950408889634f, 12582912.f);
    float n = t - 12582912.f;
    float f = fmaf(n, -0.693145751953125f, x);
    f = fmaf(n, -1.428606765330187e-06f, f);
    float p = 1.3888889e-3f;
    p = fmaf(p, f, 8.3333338e-3f);
    p = fmaf(p, f, 4.1666668e-2f);
    p = fmaf(p, f, 1.6666667e-1f);
    p = fmaf(p, f, 5.0e-1f);
    p = fmaf(p, f, 1.0f);
    p = fmaf(p, f, 1.0f);
    int i = (int)n;
    return __int_as_float(__float_as_int(p) + (i << 23));
}
__device__ __forceinline__ uint32_t packh2(float a, float b) {
    __half2 t = __floats2half2_rn(a, b);
    return *reinterpret_cast<uint32_t*>(&t);
}
__device__ __forceinline__ void hsplit2(float a, float b, uint32_t& h, uint32_t& l) {
    __half ha = __float2half_rn(a), hb = __float2half_rn(b);
    __half2 hh = __halves2half2(ha, hb);
    h = *reinterpret_cast<uint32_t*>(&hh);
    l = packh2(a - __half2float(ha), b - __half2float(hb));
}

// ======================== converter kernels ==============================
__global__ void __launch_bounds__(256)
conv_in_kernel(const float* __restrict__ q, const float* __restrict__ k,
               const float* __restrict__ v)
{
    const int z = blockIdx.y;
    const float* src = (z == 0) ? q : (z == 1) ? k : v;
    __half* dhi = g_inhi[z];
    size_t base = ((size_t)blockIdx.x * 256 + threadIdx.x) * 8;
    float4 a = *(const float4*)(src + base);
    float4 b = *(const float4*)(src + base + 4);
    __half hi[8];
    float xs[8] = {a.x, a.y, a.z, a.w, b.x, b.y, b.z, b.w};
#pragma unroll
    for (int i = 0; i < 8; i++) hi[i] = __float2half_rn(xs[i]);
    *(uint4*)(dhi + base) = *(uint4*)hi;
}

__global__ void __launch_bounds__(256)
conv_w_kernel(const float* __restrict__ Wq, const float* __restrict__ Wk,
              const float* __restrict__ Wv, const float* __restrict__ Wfc)
{
    __shared__ float tile[32][33];
    const int z = blockIdx.z;
    const float* W = (z == 0) ? Wq : (z == 1) ? Wk : (z == 2) ? Wv : Wfc;
    __half* dh = g_wth[z];
    const int n0 = blockIdx.x * 32, k0 = blockIdx.y * 32;
    const int c = threadIdx.x & 31, r0 = (threadIdx.x >> 5) * 4;
#pragma unroll
    for (int rr = 0; rr < 4; rr++)
        tile[r0 + rr][c] = W[(size_t)(k0 + r0 + rr) * DM + n0 + c];
    __syncthreads();
#pragma unroll
    for (int rr = 0; rr < 4; rr++) {
        int n = n0 + r0 + rr;
        dh[(size_t)n * DM + k0 + c] = __float2half_rn(tile[c][r0 + rr]);
    }
}

// ======================== fp16 HMMA GEMM (cp.async, 1-term) ==============
#define TSX 40
#define TILE_B (128 * TSX * 2)
#define GEMM_SMEM_BYTES (2 * 2 * TILE_B)   // 40960

__global__ void __launch_bounds__(256, 2)
mma_gemm_kernel(const float* __restrict__ bq, const float* __restrict__ bk,
                const float* __restrict__ bv, const float* __restrict__ bfc,
                int is_fc)
{
    extern __shared__ char dyn[];
    const uint32_t sb = smem_u32(dyn);
    const int tid = threadIdx.x, wid = tid >> 5, lane = tid & 31;
    const int m0 = blockIdx.x * 128, n0 = blockIdx.y * 128;
    const int z = blockIdx.z;

    const __half *Ah, *Bh;
    const float* bias;
    if (is_fc) {
        Ah = g_aohi; Bh = g_wth[3]; bias = bfc;
    } else {
        Ah = g_inhi[z]; Bh = g_wth[z];
        bias = (z == 0) ? bq : (z == 1) ? bk : bv;
    }
    const __half* srcs[2] = { Ah + (size_t)m0 * DM, Bh + (size_t)n0 * DM };

    const int wm = (wid & 3) * 32;
    const int wn = (wid >> 2) * 64;

    float acc[2][8][4];
#pragma unroll
    for (int ms = 0; ms < 2; ms++)
#pragma unroll
        for (int ns = 0; ns < 8; ns++)
#pragma unroll
            for (int c = 0; c < 4; c++) acc[ms][ns][c] = 0.f;

    const int r_ld = tid >> 2;
    const int c_ld = (tid & 3) * 8;

    auto issue_tile = [&](int buf, int k0) {
#pragma unroll
        for (int t = 0; t < 2; t++)
#pragma unroll
            for (int u = 0; u < 2; u++) {
                uint32_t sa = sb + buf * (2 * TILE_B) + t * TILE_B +
                              ((r_ld + u * 64) * TSX + c_ld) * 2;
                CPA16(sa, srcs[t] + (size_t)(r_ld + u * 64) * DM + k0 + c_ld);
            }
        CPA_COMMIT();
    };

    issue_tile(0, 0);
    CPA_WAIT0();
    __syncthreads();

    const int rowA = wm + (lane & 15);
    const int colA = (lane >> 4) << 3;
    const int rowB = wn + (lane & 7) + ((lane >> 4) << 3);
    const int colB = ((lane >> 3) & 1) << 3;

    for (int step = 0; step < 32; step++) {
        const int buf = step & 1;
        const uint32_t base = sb + buf * (2 * TILE_B);
        const int has_next = (step + 1 < 32);
        if (has_next) issue_tile(buf ^ 1, (step + 1) * 32);

#pragma unroll
        for (int kh = 0; kh < 32; kh += 16) {
            uint32_t ah[2][4];
#pragma unroll
            for (int ms = 0; ms < 2; ms++) {
                uint32_t off = ((rowA + ms * 16) * TSX + kh + colA) * 2;
                ldsm4(ah[ms], base + off);
            }
            uint32_t bh[8][2];
#pragma unroll
            for (int np = 0; np < 4; np++) {
                uint32_t off = ((rowB + np * 16) * TSX + kh + colB) * 2;
                uint32_t t4[4];
                ldsm4(t4, base + TILE_B + off);
                bh[2 * np][0] = t4[0]; bh[2 * np][1] = t4[1];
                bh[2 * np + 1][0] = t4[2]; bh[2 * np + 1][1] = t4[3];
            }
#pragma unroll
            for (int ms = 0; ms < 2; ms++)
#pragma unroll
                for (int ns = 0; ns < 8; ns++)
                    mma_f16(acc[ms][ns], ah[ms], bh[ns][0], bh[ns][1]);
        }
        if (has_next) {
            CPA_WAIT0();
            __syncthreads();
        }
    }

    const int qrow = lane >> 2;
    const int qcol = (lane & 3) * 2;
    const float scale = (!is_fc && z == 0) ? 0.125f : 1.0f;
#pragma unroll
    for (int ms = 0; ms < 2; ms++) {
#pragma unroll
        for (int ns = 0; ns < 8; ns++) {
            const int ncol = n0 + wn + ns * 8 + qcol;
            const float b0 = bias[ncol], b1 = bias[ncol + 1];
#pragma unroll
            for (int half = 0; half < 2; half++) {
                const int m = m0 + wm + ms * 16 + qrow + half * 8;
                float x0 = (acc[ms][ns][2 * half] + b0) * scale;
                float x1 = (acc[ms][ns][2 * half + 1] + b1) * scale;
                if (is_fc) {
                    *(float2*)(g_fc + (size_t)m * DM + ncol) = make_float2(x0, x1);
                } else {
                    const int l = m >> 1, bb = m & 1;
                    const int h = ncol >> 6, dkb = ncol & 63;
                    if (z == 0) {
                        // Q stored as exact hi/lo split
                        size_t idx = ((size_t)(h * NB + bb) * L_SEQ + l) * DHEAD + dkb;
                        uint32_t ph, pl;
                        hsplit2(x0, x1, ph, pl);
                        *(uint32_t*)(g_qh + idx) = ph;
                        *(uint32_t*)(g_ql + idx) = pl;
                    } else if (z == 1) {
                        size_t idx = ((size_t)(h * NB + bb) * L_SEQ + l) * DHEAD + dkb;
                        *(uint32_t*)(g_kh + idx) = packh2(x0, x1);
                    } else {
                        size_t base2 = ((size_t)(h * NB + bb) * DHEAD + dkb) * L_SEQ + l;
                        g_vth[base2] = __float2half_rn(x0);
                        g_vth[base2 + L_SEQ] = __float2half_rn(x1);
                    }
                }
            }
        }
    }
}

// =========================================================================
// fp16 HMMA banded attention (R11 structure, measured 59.8us):
// S = (Qh+Ql) Kh^T (2-term Q, exact) ;  O = Ph Vh (1-term).
// Writes unnormalized p to gmem; row sums to g_rowl.
// =========================================================================
#define QKS 72           // Q/K smem row stride (halves)
#define VTS 136          // Vt smem row stride
#define OFF_QH 0
#define OFF_QL 18432
#define OFF_KH 36864
#define OFF_VH 55296
#define ATTN_SMEM_BYTES (55296 + 64 * VTS * 2)   // 72704

__global__ void __launch_bounds__(256, 2)
attn_kernel(float* __restrict__ attn_raw)
{
    extern __shared__ char dyn[];
    const uint32_t sb = smem_u32(dyn);
    const int tid = threadIdx.x, wid = tid >> 5, lane = tid & 31;
    const int w16 = wid * 16;
    const int i0 = blockIdx.x * 128;
    const int hb = blockIdx.y;

    const __half* Qh = g_qh + (size_t)hb * L_SEQ * DHEAD;
    const __half* Ql = g_ql + (size_t)hb * L_SEQ * DHEAD;
    const __half* Kh = g_kh + (size_t)hb * L_SEQ * DHEAD;
    const __half* Vh = g_vth + (size_t)hb * DHEAD * L_SEQ;
    float* rawbase = attn_raw + (size_t)hb * L_SEQ * L_SEQ;

    // load Q tile (persistent)
    {
        const __half* src = Qh + (size_t)i0 * DHEAD;
        const __half* srl = Ql + (size_t)i0 * DHEAD;
#pragma unroll
        for (int u = 0; u < 4; u++) {
            int idx = tid + u * 256;
            int r = idx >> 3, c = idx & 7;
            *(uint4*)(dyn + OFF_QH + (r * QKS + c * 8) * 2) =
                *(const uint4*)(src + (size_t)r * DHEAD + c * 8);
            *(uint4*)(dyn + OFF_QL + (r * QKS + c * 8) * 2) =
                *(const uint4*)(srl + (size_t)r * DHEAD + c * 8);
        }
    }

    const int ir0 = i0 + w16 + (lane >> 2);
    const int ir1 = ir0 + 8;
    const int jco = 2 * (lane & 3);

    const uint32_t qoff = ((w16 + (lane & 15)) * QKS + ((lane >> 4) << 3)) * 2;
    const uint32_t brow = (lane & 7) + ((lane >> 4) << 3);
    const uint32_t bcol = ((lane >> 3) & 1) << 3;

    float O[8][4];
#pragma unroll
    for (int n = 0; n < 8; n++)
#pragma unroll
        for (int e = 0; e < 4; e++) O[n][e] = 0.f;
    float sum0 = 0.f, sum1 = 0.f;

    for (int cch = 0; cch < 3; cch++) {
        int j0 = i0 + (cch - 1) * 128;
        if (j0 < 0 || j0 >= L_SEQ) continue;
        __syncthreads();     // prev chunk K/V fully consumed
        {
#pragma unroll
            for (int u = 0; u < 4; u++) {
                int idx = tid + u * 256;
                int r = idx >> 3, c = idx & 7;
                *(uint4*)(dyn + OFF_KH + (r * QKS + c * 8) * 2) =
                    *(const uint4*)(Kh + (size_t)(j0 + r) * DHEAD + c * 8);
            }
#pragma unroll
            for (int u = 0; u < 4; u++) {
                int idx = tid + u * 256;
                int r = idx >> 4, c = idx & 15;
                *(uint4*)(dyn + OFF_VH + (r * VTS + c * 8) * 2) =
                    *(const uint4*)(Vh + (size_t)r * L_SEQ + j0 + c * 8);
            }
        }
        __syncthreads();

#pragma unroll
        for (int half = 0; half < 2; half++) {
            // ---- S = Q K^T for 64 j-cols (2-term Q) ----
            float Sv[8][4];
#pragma unroll
            for (int n = 0; n < 8; n++)
#pragma unroll
                for (int e = 0; e < 4; e++) Sv[n][e] = 0.f;
#pragma unroll
            for (int ks = 0; ks < 4; ks++) {
                uint32_t ah[4], al[4];
                ldsm4(ah, sb + OFF_QH + qoff + ks * 32);
                ldsm4(al, sb + OFF_QL + qoff + ks * 32);
#pragma unroll
                for (int n2 = 0; n2 < 4; n2++) {
                    uint32_t off = ((half * 64 + n2 * 16 + brow) * QKS + ks * 16 + bcol) * 2;
                    uint32_t kh4[4];
                    ldsm4(kh4, sb + OFF_KH + off);
                    mma_f16(Sv[2 * n2], ah, kh4[0], kh4[1]);
                    mma_f16(Sv[2 * n2], al, kh4[0], kh4[1]);
                    mma_f16(Sv[2 * n2 + 1], ah, kh4[2], kh4[3]);
                    mma_f16(Sv[2 * n2 + 1], al, kh4[2], kh4[3]);
                }
            }

            // ---- mask + exp (m=0) + gmem p + row sums ----
#pragma unroll
            for (int n = 0; n < 8; n++) {
                int j = j0 + half * 64 + n * 8 + jco;
                int d0 = ir0 - j, d1 = ir1 - j;
                float p00 = (d0 >= -SPAN_W && d0 <= SPAN_W) ? fexp(Sv[n][0]) : 0.f;
                float p01 = (d0 - 1 >= -SPAN_W && d0 - 1 <= SPAN_W) ? fexp(Sv[n][1]) : 0.f;
                float p10 = (d1 >= -SPAN_W && d1 <= SPAN_W) ? fexp(Sv[n][2]) : 0.f;
                float p11 = (d1 - 1 >= -SPAN_W && d1 - 1 <= SPAN_W) ? fexp(Sv[n][3]) : 0.f;
                sum0 += p00 + p01;
                sum1 += p10 + p11;
                *(float2*)(rawbase + (size_t)ir0 * L_SEQ + j) = make_float2(p00, p01);
                *(float2*)(rawbase + (size_t)ir1 * L_SEQ + j) = make_float2(p10, p11);
                Sv[n][0] = p00; Sv[n][1] = p01; Sv[n][2] = p10; Sv[n][3] = p11;
            }

            // ---- O += P V (single-term P, A-fragments from registers) ----
#pragma unroll
            for (int t = 0; t < 4; t++) {
                uint32_t af[4];
                af[0] = packh2(Sv[2 * t][0], Sv[2 * t][1]);
                af[1] = packh2(Sv[2 * t][2], Sv[2 * t][3]);
                af[2] = packh2(Sv[2 * t + 1][0], Sv[2 * t + 1][1]);
                af[3] = packh2(Sv[2 * t + 1][2], Sv[2 * t + 1][3]);
#pragma unroll
                for (int n2 = 0; n2 < 4; n2++) {
                    uint32_t off = ((n2 * 16 + brow) * VTS + half * 64 + t * 16 + bcol) * 2;
                    uint32_t vh4[4];
                    ldsm4(vh4, sb + OFF_VH + off);
                    mma_f16(O[2 * n2], af, vh4[0], vh4[1]);
                    mma_f16(O[2 * n2 + 1], af, vh4[2], vh4[3]);
                }
            }
        }
    }

    sum0 += __shfl_xor_sync(0xffffffffu, sum0, 1);
    sum0 += __shfl_xor_sync(0xffffffffu, sum0, 2);
    sum1 += __shfl_xor_sync(0xffffffffu, sum1, 1);
    sum1 += __shfl_xor_sync(0xffffffffu, sum1, 2);
    const float inv0 = 1.f / sum0;
    const float inv1 = 1.f / sum1;
    if ((lane & 3) == 0) {
        g_rowl[hb * L_SEQ + ir0] = sum0;
        g_rowl[hb * L_SEQ + ir1] = sum1;
    }

    // epilogue: attnout single fp16  [l b][h dv]
    const int h = hb >> 1, bb = hb & 1;
#pragma unroll
    for (int n = 0; n < 8; n++) {
        int dv = n * 8 + jco;
        size_t i0x = ((size_t)ir0 * NB + bb) * DM + h * DHEAD + dv;
        size_t i1x = ((size_t)ir1 * NB + bb) * DM + h * DHEAD + dv;
        *(uint32_t*)(g_aohi + i0x) = packh2(O[n][0] * inv0, O[n][1] * inv0);
        *(uint32_t*)(g_aohi + i1x) = packh2(O[n][2] * inv1, O[n][3] * inv1);
    }
}

// =========================================================================
// Normalize: per-8-group band test; only overlapping groups load.
// =========================================================================
__global__ void __launch_bounds__(256)
attn_norm_kernel(float* __restrict__ attn)
{
    const int row = blockIdx.x;
    const int i = row & (L_SEQ - 1);
    float* p = attn + (size_t)row * L_SEQ;
    const int j0 = threadIdx.x * 8;
    const bool overlap = (j0 + 7 >= i - SPAN_W) && (j0 <= i + SPAN_W);
    if (!overlap) {
        float4 zz = make_float4(0.f, 0.f, 0.f, 0.f);
        *(float4*)&p[j0] = zz;
        *(float4*)&p[j0 + 4] = zz;
        return;
    }
    const float inv = 1.f / g_rowl[row];
    float4 a = *(const float4*)&p[j0];
    float4 b = *(const float4*)&p[j0 + 4];
    float out[8] = {a.x, a.y, a.z, a.w, b.x, b.y, b.z, b.w};
#pragma unroll
    for (int u = 0; u < 8; u++) {
        int d = i - (j0 + u);
        out[u] = (d >= -SPAN_W && d <= SPAN_W) ? out[u] * inv : 0.f;
    }
    *(float4*)&p[j0]     = make_float4(out[0], out[1], out[2], out[3]);
    *(float4*)&p[j0 + 4] = make_float4(out[4], out[5], out[6], out[7]);
}

// =========================================================================
// Residual + LayerNorm.
// =========================================================================
__global__ void __launch_bounds__(256)
ln_kernel(const float* __restrict__ query, const float* __restrict__ gamma,
          const float* __restrict__ beta, float* __restrict__ y)
{
    __shared__ float red[16];
    const int row = blockIdx.x;
    const int t = threadIdx.x;

    float4 f = *(const float4*)&g_fc[(size_t)row * DM + t * 4];
    float4 q = *(const float4*)&query[(size_t)row * DM + t * 4];
    float v0 = f.x + q.x, v1 = f.y + q.y, v2 = f.z + q.z, v3 = f.w + q.w;

    float s = v0 + v1 + v2 + v3;
    float s2 = v0 * v0 + v1 * v1 + v2 * v2 + v3 * v3;
#pragma unroll
    for (int off = 16; off > 0; off >>= 1) {
        s  += __shfl_xor_sync(0xffffffffu, s, off);
        s2 += __shfl_xor_sync(0xffffffffu, s2, off);
    }
    const int warp = t >> 5, lane = t & 31;
    if (lane == 0) { red[warp] = s; red[warp + 8] = s2; }
    __syncthreads();
    if (t < 32) {
        float a  = (lane < 8) ? red[lane] : 0.f;
        float b2 = (lane < 8) ? red[lane + 8] : 0.f;
#pragma unroll
        for (int off = 4; off > 0; off >>= 1) {
            a  += __shfl_xor_sync(0xffffffffu, a, off);
            b2 += __shfl_xor_sync(0xffffffffu, b2, off);
        }
        if (lane == 0) { red[0] = a; red[1] = b2; }
    }
    __syncthreads();
    const float mean = red[0] * (1.f / DM);
    const float var  = red[1] * (1.f / DM) - mean * mean;
    const float rstd = rsqrtf(var + 1e-5f);

    float4 g  = *(const float4*)&gamma[t * 4];
    float4 be = *(const float4*)&beta[t * 4];
    float4 o;
    o.x = (v0 - mean) * rstd * g.x + be.x;
    o.y = (v1 - mean) * rstd * g.y + be.y;
    o.z = (v2 - mean) * rstd * g.z + be.z;
    o.w = (v3 - mean) * rstd * g.w + be.w;
    *(float4*)&y[(size_t)row * DM + t * 4] = o;
}

// =========================================================================
extern "C" void kernel_launch(void* const* d_in, const int* in_sizes, int n_in,
                              void* d_out, int out_size)
{
    const float* query = (const float*)d_in[0];
    const float* key   = (const float*)d_in[1];
    const float* value = (const float*)d_in[2];
    const float* Wq    = (const float*)d_in[3];
    const float* bq    = (const float*)d_in[4];
    const float* Wk    = (const float*)d_in[5];
    const float* bk    = (const float*)d_in[6];
    const float* Wv    = (const float*)d_in[7];
    const float* bv    = (const float*)d_in[8];
    const float* Wfc   = (const float*)d_in[9];
    const float* bfc   = (const float*)d_in[10];
    const float* gamma = (const float*)d_in[11];
    const float* beta  = (const float*)d_in[12];

    float* y_out = (float*)d_out;
    float* attn_out = y_out + (size_t)L_SEQ * NB * DM;

    cudaFuncSetAttribute(attn_kernel,
                         cudaFuncAttributeMaxDynamicSharedMemorySize,
                         ATTN_SMEM_BYTES);
    cudaFuncSetAttribute(mma_gemm_kernel,
                         cudaFuncAttributeMaxDynamicSharedMemorySize,
                         GEMM_SMEM_BYTES);

    conv_w_kernel<<<dim3(DM / 32, DM / 32, 4), 256>>>(Wq, Wk, Wv, Wfc);
    conv_in_kernel<<<dim3(MROWS * DM / 2048, 3), 256>>>(query, key, value);

    mma_gemm_kernel<<<dim3(MROWS / 128, DM / 128, 3), 256, GEMM_SMEM_BYTES>>>(
        bq, bk, bv, bfc, 0);

    attn_kernel<<<dim3(L_SEQ / 128, HB), 256, ATTN_SMEM_BYTES>>>(attn_out);

    mma_gemm_kernel<<<dim3(MROWS / 128, DM / 128, 1), 256, GEMM_SMEM_BYTES>>>(
        bq, bk, bv, bfc, 1);

    ln_kernel<<<MROWS, 256>>>(query, gamma, beta, y_out);

    attn_norm_kernel<<<HB * L_SEQ, 256>>>(attn_out);
}

// round 17
// speedup vs baseline: 1.4643x; 1.0067x over previous
#include <cuda_runtime.h>
#include <cuda_fp16.h>
#include <math.h>
#include <float.h>
#include <stdint.h>

#define L_SEQ 2048
#define NB 2
#define DM 1024
#define NH 16
#define DHEAD 64
#define SPAN_W 128
#define MROWS (L_SEQ * NB)          // 4096
#define HB (NH * NB)                // 32

// ---------------- static scratch (no allocations allowed) ----------------
__device__ float g_fc[MROWS * DM];               // FC output (pre-LN)
__device__ float g_rowl[HB * L_SEQ];             // softmax row sum

// fp16 operands (activations/weights single-rounded)
__device__ __half g_inhi[3][MROWS * DM];         // q/k/v inputs
__device__ __half g_wth[4][DM * DM];             // W^T [n][k]
__device__ __half g_aohi[MROWS * DM];            // attnout
// projected Q (x0.125) hi/lo (exact split) + K single, head-major [hb][l][dk]
__device__ __half g_qh[HB * L_SEQ * DHEAD];
__device__ __half g_ql[HB * L_SEQ * DHEAD];
__device__ __half g_kh[HB * L_SEQ * DHEAD];
// projected V transposed [hb][dv][l]
__device__ __half g_vth[HB * DHEAD * L_SEQ];

// ---------------- helpers ----------------
__device__ __forceinline__ uint32_t smem_u32(const void* p) {
    uint32_t a;
    asm("{ .reg .u64 t; cvta.to.shared.u64 t, %1; cvt.u32.u64 %0, t; }"
        : "=r"(a) : "l"(p));
    return a;
}
__device__ __forceinline__ void ldsm4(uint32_t (&r)[4], uint32_t addr) {
    asm volatile("ldmatrix.sync.aligned.m8n8.x4.shared.b16 {%0,%1,%2,%3}, [%4];"
                 : "=r"(r[0]), "=r"(r[1]), "=r"(r[2]), "=r"(r[3]) : "r"(addr));
}
__device__ __forceinline__ void mma_f16(float (&d)[4], const uint32_t (&a)[4],
                                        uint32_t b0, uint32_t b1) {
    asm volatile(
        "mma.sync.aligned.m16n8k16.row.col.f32.f16.f16.f32 "
        "{%0,%1,%2,%3}, {%4,%5,%6,%7}, {%8,%9}, {%0,%1,%2,%3};"
        : "+f"(d[0]), "+f"(d[1]), "+f"(d[2]), "+f"(d[3])
        : "r"(a[0]), "r"(a[1]), "r"(a[2]), "r"(a[3]), "r"(b0), "r"(b1));
}
#define CPA16(saddr, gptr) \
    asm volatile("cp.async.cg.shared.global [%0], [%1], 16;" \
                 :: "r"(saddr), "l"(__cvta_generic_to_global(gptr)) : "memory")
#define CPA_COMMIT() asm volatile("cp.async.commit_group;" ::: "memory")
#define CPA_WAIT0()  asm volatile("cp.async.wait_group 0;" ::: "memory")

// fast exp on FMA pipe, ~1e-7 rel (|x| < 80)
__device__ __forceinline__ float fexp(float x) {
    x = fmaxf(x, -80.f);
    float t = fmaf(x, 1.4426950408889634f, 12582912.f);
    float n = t - 12582912.f;
    float f = fmaf(n, -0.693145751953125f, x);
    f = fmaf(n, -1.428606765330187e-06f, f);
    float p = 1.3888889e-3f;
    p = fmaf(p, f, 8.3333338e-3f);
    p = fmaf(p, f, 4.1666668e-2f);
    p = fmaf(p, f, 1.6666667e-1f);
    p = fmaf(p, f, 5.0e-1f);
    p = fmaf(p, f, 1.0f);
    p = fmaf(p, f, 1.0f);
    int i = (int)n;
    return __int_as_float(__float_as_int(p) + (i << 23));
}
__device__ __forceinline__ uint32_t packh2(float a, float b) {
    __half2 t = __floats2half2_rn(a, b);
    return *reinterpret_cast<uint32_t*>(&t);
}
__device__ __forceinline__ void hsplit2(float a, float b, uint32_t& h, uint32_t& l) {
    __half ha = __float2half_rn(a), hb = __float2half_rn(b);
    __half2 hh = __halves2half2(ha, hb);
    h = *reinterpret_cast<uint32_t*>(&hh);
    l = packh2(a - __half2float(ha), b - __half2float(hb));
}

// ======================== converter kernels ==============================
__global__ void __launch_bounds__(256)
conv_in_kernel(const float* __restrict__ q, const float* __restrict__ k,
               const float* __restrict__ v)
{
    const int z = blockIdx.y;
    const float* src = (z == 0) ? q : (z == 1) ? k : v;
    __half* dhi = g_inhi[z];
    size_t base = ((size_t)blockIdx.x * 256 + threadIdx.x) * 8;
    float4 a = *(const float4*)(src + base);
    float4 b = *(const float4*)(src + base + 4);
    __half hi[8];
    float xs[8] = {a.x, a.y, a.z, a.w, b.x, b.y, b.z, b.w};
#pragma unroll
    for (int i = 0; i < 8; i++) hi[i] = __float2half_rn(xs[i]);
    *(uint4*)(dhi + base) = *(uint4*)hi;
}

__global__ void __launch_bounds__(256)
conv_w_kernel(const float* __restrict__ Wq, const float* __restrict__ Wk,
              const float* __restrict__ Wv, const float* __restrict__ Wfc)
{
    __shared__ float tile[32][33];
    const int z = blockIdx.z;
    const float* W = (z == 0) ? Wq : (z == 1) ? Wk : (z == 2) ? Wv : Wfc;
    __half* dh = g_wth[z];
    const int n0 = blockIdx.x * 32, k0 = blockIdx.y * 32;
    const int c = threadIdx.x & 31, r0 = (threadIdx.x >> 5) * 4;
#pragma unroll
    for (int rr = 0; rr < 4; rr++)
        tile[r0 + rr][c] = W[(size_t)(k0 + r0 + rr) * DM + n0 + c];
    __syncthreads();
#pragma unroll
    for (int rr = 0; rr < 4; rr++) {
        int n = n0 + r0 + rr;
        dh[(size_t)n * DM + k0 + c] = __float2half_rn(tile[c][r0 + rr]);
    }
}

// ======================== fp16 HMMA GEMM (cp.async, 1-term) ==============
#define TSX 40
#define TILE_B (128 * TSX * 2)
#define GEMM_SMEM_BYTES (2 * 2 * TILE_B)   // 40960

__global__ void __launch_bounds__(256, 2)
mma_gemm_kernel(const float* __restrict__ bq, const float* __restrict__ bk,
                const float* __restrict__ bv, const float* __restrict__ bfc,
                int is_fc)
{
    extern __shared__ char dyn[];
    const uint32_t sb = smem_u32(dyn);
    const int tid = threadIdx.x, wid = tid >> 5, lane = tid & 31;
    const int m0 = blockIdx.x * 128, n0 = blockIdx.y * 128;
    const int z = blockIdx.z;

    const __half *Ah, *Bh;
    const float* bias;
    if (is_fc) {
        Ah = g_aohi; Bh = g_wth[3]; bias = bfc;
    } else {
        Ah = g_inhi[z]; Bh = g_wth[z];
        bias = (z == 0) ? bq : (z == 1) ? bk : bv;
    }
    const __half* srcs[2] = { Ah + (size_t)m0 * DM, Bh + (size_t)n0 * DM };

    const int wm = (wid & 3) * 32;
    const int wn = (wid >> 2) * 64;

    float acc[2][8][4];
#pragma unroll
    for (int ms = 0; ms < 2; ms++)
#pragma unroll
        for (int ns = 0; ns < 8; ns++)
#pragma unroll
            for (int c = 0; c < 4; c++) acc[ms][ns][c] = 0.f;

    const int r_ld = tid >> 2;
    const int c_ld = (tid & 3) * 8;

    auto issue_tile = [&](int buf, int k0) {
#pragma unroll
        for (int t = 0; t < 2; t++)
#pragma unroll
            for (int u = 0; u < 2; u++) {
                uint32_t sa = sb + buf * (2 * TILE_B) + t * TILE_B +
                              ((r_ld + u * 64) * TSX + c_ld) * 2;
                CPA16(sa, srcs[t] + (size_t)(r_ld + u * 64) * DM + k0 + c_ld);
            }
        CPA_COMMIT();
    };

    issue_tile(0, 0);
    CPA_WAIT0();
    __syncthreads();

    const int rowA = wm + (lane & 15);
    const int colA = (lane >> 4) << 3;
    const int rowB = wn + (lane & 7) + ((lane >> 4) << 3);
    const int colB = ((lane >> 3) & 1) << 3;

    for (int step = 0; step < 32; step++) {
        const int buf = step & 1;
        const uint32_t base = sb + buf * (2 * TILE_B);
        const int has_next = (step + 1 < 32);
        if (has_next) issue_tile(buf ^ 1, (step + 1) * 32);

#pragma unroll
        for (int kh = 0; kh < 32; kh += 16) {
            uint32_t ah[2][4];
#pragma unroll
            for (int ms = 0; ms < 2; ms++) {
                uint32_t off = ((rowA + ms * 16) * TSX + kh + colA) * 2;
                ldsm4(ah[ms], base + off);
            }
            uint32_t bh[8][2];
#pragma unroll
            for (int np = 0; np < 4; np++) {
                uint32_t off = ((rowB + np * 16) * TSX + kh + colB) * 2;
                uint32_t t4[4];
                ldsm4(t4, base + TILE_B + off);
                bh[2 * np][0] = t4[0]; bh[2 * np][1] = t4[1];
                bh[2 * np + 1][0] = t4[2]; bh[2 * np + 1][1] = t4[3];
            }
#pragma unroll
            for (int ms = 0; ms < 2; ms++)
#pragma unroll
                for (int ns = 0; ns < 8; ns++)
                    mma_f16(acc[ms][ns], ah[ms], bh[ns][0], bh[ns][1]);
        }
        if (has_next) {
            CPA_WAIT0();
            __syncthreads();
        }
    }

    const int qrow = lane >> 2;
    const int qcol = (lane & 3) * 2;
    const float scale = (!is_fc && z == 0) ? 0.125f : 1.0f;
#pragma unroll
    for (int ms = 0; ms < 2; ms++) {
#pragma unroll
        for (int ns = 0; ns < 8; ns++) {
            const int ncol = n0 + wn + ns * 8 + qcol;
            const float b0 = bias[ncol], b1 = bias[ncol + 1];
#pragma unroll
            for (int half = 0; half < 2; half++) {
                const int m = m0 + wm + ms * 16 + qrow + half * 8;
                float x0 = (acc[ms][ns][2 * half] + b0) * scale;
                float x1 = (acc[ms][ns][2 * half + 1] + b1) * scale;
                if (is_fc) {
                    *(float2*)(g_fc + (size_t)m * DM + ncol) = make_float2(x0, x1);
                } else {
                    const int l = m >> 1, bb = m & 1;
                    const int h = ncol >> 6, dkb = ncol & 63;
                    if (z == 0) {
                        size_t idx = ((size_t)(h * NB + bb) * L_SEQ + l) * DHEAD + dkb;
                        uint32_t ph, pl;
                        hsplit2(x0, x1, ph, pl);
                        *(uint32_t*)(g_qh + idx) = ph;
                        *(uint32_t*)(g_ql + idx) = pl;
                    } else if (z == 1) {
                        size_t idx = ((size_t)(h * NB + bb) * L_SEQ + l) * DHEAD + dkb;
                        *(uint32_t*)(g_kh + idx) = packh2(x0, x1);
                    } else {
                        size_t base2 = ((size_t)(h * NB + bb) * DHEAD + dkb) * L_SEQ + l;
                        g_vth[base2] = __float2half_rn(x0);
                        g_vth[base2 + L_SEQ] = __float2half_rn(x1);
                    }
                }
            }
        }
    }
}

// =========================================================================
// fp16 HMMA banded attention (measured 60us): S = (Qh+Ql) Kh^T ; O = P Vh.
// Writes unnormalized p (0 at masked in-coverage positions); sums to g_rowl.
// =========================================================================
#define QKS 72           // Q/K smem row stride (halves)
#define VTS 136          // Vt smem row stride
#define OFF_QH 0
#define OFF_QL 18432
#define OFF_KH 36864
#define OFF_VH 55296
#define ATTN_SMEM_BYTES (55296 + 64 * VTS * 2)   // 72704

__global__ void __launch_bounds__(256, 2)
attn_kernel(float* __restrict__ attn_raw)
{
    extern __shared__ char dyn[];
    const uint32_t sb = smem_u32(dyn);
    const int tid = threadIdx.x, wid = tid >> 5, lane = tid & 31;
    const int w16 = wid * 16;
    const int i0 = blockIdx.x * 128;
    const int hb = blockIdx.y;

    const __half* Qh = g_qh + (size_t)hb * L_SEQ * DHEAD;
    const __half* Ql = g_ql + (size_t)hb * L_SEQ * DHEAD;
    const __half* Kh = g_kh + (size_t)hb * L_SEQ * DHEAD;
    const __half* Vh = g_vth + (size_t)hb * DHEAD * L_SEQ;
    float* rawbase = attn_raw + (size_t)hb * L_SEQ * L_SEQ;

    // load Q tile (persistent)
    {
        const __half* src = Qh + (size_t)i0 * DHEAD;
        const __half* srl = Ql + (size_t)i0 * DHEAD;
#pragma unroll
        for (int u = 0; u < 4; u++) {
            int idx = tid + u * 256;
            int r = idx >> 3, c = idx & 7;
            *(uint4*)(dyn + OFF_QH + (r * QKS + c * 8) * 2) =
                *(const uint4*)(src + (size_t)r * DHEAD + c * 8);
            *(uint4*)(dyn + OFF_QL + (r * QKS + c * 8) * 2) =
                *(const uint4*)(srl + (size_t)r * DHEAD + c * 8);
        }
    }

    const int ir0 = i0 + w16 + (lane >> 2);
    const int ir1 = ir0 + 8;
    const int jco = 2 * (lane & 3);

    const uint32_t qoff = ((w16 + (lane & 15)) * QKS + ((lane >> 4) << 3)) * 2;
    const uint32_t brow = (lane & 7) + ((lane >> 4) << 3);
    const uint32_t bcol = ((lane >> 3) & 1) << 3;

    float O[8][4];
#pragma unroll
    for (int n = 0; n < 8; n++)
#pragma unroll
        for (int e = 0; e < 4; e++) O[n][e] = 0.f;
    float sum0 = 0.f, sum1 = 0.f;

    for (int cch = 0; cch < 3; cch++) {
        int j0 = i0 + (cch - 1) * 128;
        if (j0 < 0 || j0 >= L_SEQ) continue;
        __syncthreads();     // prev chunk K/V fully consumed
        {
#pragma unroll
            for (int u = 0; u < 4; u++) {
                int idx = tid + u * 256;
                int r = idx >> 3, c = idx & 7;
                *(uint4*)(dyn + OFF_KH + (r * QKS + c * 8) * 2) =
                    *(const uint4*)(Kh + (size_t)(j0 + r) * DHEAD + c * 8);
            }
#pragma unroll
            for (int u = 0; u < 4; u++) {
                int idx = tid + u * 256;
                int r = idx >> 4, c = idx & 15;
                *(uint4*)(dyn + OFF_VH + (r * VTS + c * 8) * 2) =
                    *(const uint4*)(Vh + (size_t)r * L_SEQ + j0 + c * 8);
            }
        }
        __syncthreads();

#pragma unroll
        for (int half = 0; half < 2; half++) {
            float Sv[8][4];
#pragma unroll
            for (int n = 0; n < 8; n++)
#pragma unroll
                for (int e = 0; e < 4; e++) Sv[n][e] = 0.f;
#pragma unroll
            for (int ks = 0; ks < 4; ks++) {
                uint32_t ah[4], al[4];
                ldsm4(ah, sb + OFF_QH + qoff + ks * 32);
                ldsm4(al, sb + OFF_QL + qoff + ks * 32);
#pragma unroll
                for (int n2 = 0; n2 < 4; n2++) {
                    uint32_t off = ((half * 64 + n2 * 16 + brow) * QKS + ks * 16 + bcol) * 2;
                    uint32_t kh4[4];
                    ldsm4(kh4, sb + OFF_KH + off);
                    mma_f16(Sv[2 * n2], ah, kh4[0], kh4[1]);
                    mma_f16(Sv[2 * n2], al, kh4[0], kh4[1]);
                    mma_f16(Sv[2 * n2 + 1], ah, kh4[2], kh4[3]);
                    mma_f16(Sv[2 * n2 + 1], al, kh4[2], kh4[3]);
                }
            }

#pragma unroll
            for (int n = 0; n < 8; n++) {
                int j = j0 + half * 64 + n * 8 + jco;
                int d0 = ir0 - j, d1 = ir1 - j;
                float p00 = (d0 >= -SPAN_W && d0 <= SPAN_W) ? fexp(Sv[n][0]) : 0.f;
                float p01 = (d0 - 1 >= -SPAN_W && d0 - 1 <= SPAN_W) ? fexp(Sv[n][1]) : 0.f;
                float p10 = (d1 >= -SPAN_W && d1 <= SPAN_W) ? fexp(Sv[n][2]) : 0.f;
                float p11 = (d1 - 1 >= -SPAN_W && d1 - 1 <= SPAN_W) ? fexp(Sv[n][3]) : 0.f;
                sum0 += p00 + p01;
                sum1 += p10 + p11;
                *(float2*)(rawbase + (size_t)ir0 * L_SEQ + j) = make_float2(p00, p01);
                *(float2*)(rawbase + (size_t)ir1 * L_SEQ + j) = make_float2(p10, p11);
                Sv[n][0] = p00; Sv[n][1] = p01; Sv[n][2] = p10; Sv[n][3] = p11;
            }

#pragma unroll
            for (int t = 0; t < 4; t++) {
                uint32_t af[4];
                af[0] = packh2(Sv[2 * t][0], Sv[2 * t][1]);
                af[1] = packh2(Sv[2 * t][2], Sv[2 * t][3]);
                af[2] = packh2(Sv[2 * t + 1][0], Sv[2 * t + 1][1]);
                af[3] = packh2(Sv[2 * t + 1][2], Sv[2 * t + 1][3]);
#pragma unroll
                for (int n2 = 0; n2 < 4; n2++) {
                    uint32_t off = ((n2 * 16 + brow) * VTS + half * 64 + t * 16 + bcol) * 2;
                    uint32_t vh4[4];
                    ldsm4(vh4, sb + OFF_VH + off);
                    mma_f16(O[2 * n2], af, vh4[0], vh4[1]);
                    mma_f16(O[2 * n2 + 1], af, vh4[2], vh4[3]);
                }
            }
        }
    }

    sum0 += __shfl_xor_sync(0xffffffffu, sum0, 1);
    sum0 += __shfl_xor_sync(0xffffffffu, sum0, 2);
    sum1 += __shfl_xor_sync(0xffffffffu, sum1, 1);
    sum1 += __shfl_xor_sync(0xffffffffu, sum1, 2);
    const float inv0 = 1.f / sum0;
    const float inv1 = 1.f / sum1;
    if ((lane & 3) == 0) {
        g_rowl[hb * L_SEQ + ir0] = sum0;
        g_rowl[hb * L_SEQ + ir1] = sum1;
    }

    const int h = hb >> 1, bb = hb & 1;
#pragma unroll
    for (int n = 0; n < 8; n++) {
        int dv = n * 8 + jco;
        size_t i0x = ((size_t)ir0 * NB + bb) * DM + h * DHEAD + dv;
        size_t i1x = ((size_t)ir1 * NB + bb) * DM + h * DHEAD + dv;
        *(uint32_t*)(g_aohi + i0x) = packh2(O[n][0] * inv0, O[n][1] * inv0);
        *(uint32_t*)(g_aohi + i1x) = packh2(O[n][2] * inv1, O[n][3] * inv1);
    }
}

// =========================================================================
// zero_kernel: fill out-of-coverage columns with 0.  NO dependencies —
// runs on side stream overlapped with conv/GEMM/attn.
// Coverage for row i (i0 = i & ~127): [max(0,i0-128), min(L, i0+256)).
// =========================================================================
__global__ void __launch_bounds__(256)
zero_kernel(float* __restrict__ attn)
{
    const int row = blockIdx.x;
    const int i = row & (L_SEQ - 1);
    const int i0 = i & ~127;
    const int cov0 = (i0 - 128 > 0) ? i0 - 128 : 0;
    const int cov1 = (i0 + 256 < L_SEQ) ? i0 + 256 : L_SEQ;
    const int j0 = threadIdx.x * 8;
    if (j0 + 8 <= cov0 || j0 >= cov1) {
        float* p = attn + (size_t)row * L_SEQ + j0;
        float4 zz = make_float4(0.f, 0.f, 0.f, 0.f);
        *(float4*)&p[0] = zz;
        *(float4*)&p[4] = zz;
    }
}

// =========================================================================
// band_norm_kernel: scale the coverage window by 1/rowsum (masked entries
// are already 0 from attn).  Depends on attn; overlaps FC+LN on side stream.
// =========================================================================
__global__ void __launch_bounds__(96)
band_norm_kernel(float* __restrict__ attn)
{
    const int row = blockIdx.x;
    const int i = row & (L_SEQ - 1);
    const int i0 = i & ~127;
    const int cov0 = (i0 - 128 > 0) ? i0 - 128 : 0;
    const int cov1 = (i0 + 256 < L_SEQ) ? i0 + 256 : L_SEQ;
    const int c = cov0 + threadIdx.x * 4;
    if (c >= cov1) return;
    const float inv = 1.f / g_rowl[row];
    float* p = attn + (size_t)row * L_SEQ + c;
    float4 v = *(float4*)p;
    v.x *= inv; v.y *= inv; v.z *= inv; v.w *= inv;
    *(float4*)p = v;
}

// =========================================================================
// Residual + LayerNorm.
// =========================================================================
__global__ void __launch_bounds__(256)
ln_kernel(const float* __restrict__ query, const float* __restrict__ gamma,
          const float* __restrict__ beta, float* __restrict__ y)
{
    __shared__ float red[16];
    const int row = blockIdx.x;
    const int t = threadIdx.x;

    float4 f = *(const float4*)&g_fc[(size_t)row * DM + t * 4];
    float4 q = *(const float4*)&query[(size_t)row * DM + t * 4];
    float v0 = f.x + q.x, v1 = f.y + q.y, v2 = f.z + q.z, v3 = f.w + q.w;

    float s = v0 + v1 + v2 + v3;
    float s2 = v0 * v0 + v1 * v1 + v2 * v2 + v3 * v3;
#pragma unroll
    for (int off = 16; off > 0; off >>= 1) {
        s  += __shfl_xor_sync(0xffffffffu, s, off);
        s2 += __shfl_xor_sync(0xffffffffu, s2, off);
    }
    const int warp = t >> 5, lane = t & 31;
    if (lane == 0) { red[warp] = s; red[warp + 8] = s2; }
    __syncthreads();
    if (t < 32) {
        float a  = (lane < 8) ? red[lane] : 0.f;
        float b2 = (lane < 8) ? red[lane + 8] : 0.f;
#pragma unroll
        for (int off = 4; off > 0; off >>= 1) {
            a  += __shfl_xor_sync(0xffffffffu, a, off);
            b2 += __shfl_xor_sync(0xffffffffu, b2, off);
        }
        if (lane == 0) { red[0] = a; red[1] = b2; }
    }
    __syncthreads();
    const float mean = red[0] * (1.f / DM);
    const float var  = red[1] * (1.f / DM) - mean * mean;
    const float rstd = rsqrtf(var + 1e-5f);

    float4 g  = *(const float4*)&gamma[t * 4];
    float4 be = *(const float4*)&beta[t * 4];
    float4 o;
    o.x = (v0 - mean) * rstd * g.x + be.x;
    o.y = (v1 - mean) * rstd * g.y + be.y;
    o.z = (v2 - mean) * rstd * g.z + be.z;
    o.w = (v3 - mean) * rstd * g.w + be.w;
    *(float4*)&y[(size_t)row * DM + t * 4] = o;
}

// =========================================================================
extern "C" void kernel_launch(void* const* d_in, const int* in_sizes, int n_in,
                              void* d_out, int out_size)
{
    const float* query = (const float*)d_in[0];
    const float* key   = (const float*)d_in[1];
    const float* value = (const float*)d_in[2];
    const float* Wq    = (const float*)d_in[3];
    const float* bq    = (const float*)d_in[4];
    const float* Wk    = (const float*)d_in[5];
    const float* bk    = (const float*)d_in[6];
    const float* Wv    = (const float*)d_in[7];
    const float* bv    = (const float*)d_in[8];
    const float* Wfc   = (const float*)d_in[9];
    const float* bfc   = (const float*)d_in[10];
    const float* gamma = (const float*)d_in[11];
    const float* beta  = (const float*)d_in[12];

    float* y_out = (float*)d_out;
    float* attn_out = y_out + (size_t)L_SEQ * NB * DM;

    // one-time host-object setup (streams/events are host/driver objects)
    static cudaStream_t s2 = nullptr;
    static cudaEvent_t evFork = nullptr, evAttn = nullptr, evJoin = nullptr;
    if (s2 == nullptr) {
        cudaStreamCreateWithFlags(&s2, cudaStreamNonBlocking);
        cudaEventCreateWithFlags(&evFork, cudaEventDisableTiming);
        cudaEventCreateWithFlags(&evAttn, cudaEventDisableTiming);
        cudaEventCreateWithFlags(&evJoin, cudaEventDisableTiming);
        cudaFuncSetAttribute(attn_kernel,
                             cudaFuncAttributeMaxDynamicSharedMemorySize,
                             ATTN_SMEM_BYTES);
        cudaFuncSetAttribute(mma_gemm_kernel,
                             cudaFuncAttributeMaxDynamicSharedMemorySize,
                             GEMM_SMEM_BYTES);
    }

    // fork side stream; zero-fill (no deps) overlaps the compute phase
    cudaEventRecord(evFork, 0);
    cudaStreamWaitEvent(s2, evFork, 0);
    zero_kernel<<<HB * L_SEQ, 256, 0, s2>>>(attn_out);

    // main pipeline on default stream
    conv_w_kernel<<<dim3(DM / 32, DM / 32, 4), 256>>>(Wq, Wk, Wv, Wfc);
    conv_in_kernel<<<dim3(MROWS * DM / 2048, 3), 256>>>(query, key, value);
    mma_gemm_kernel<<<dim3(MROWS / 128, DM / 128, 3), 256, GEMM_SMEM_BYTES>>>(
        bq, bk, bv, bfc, 0);
    attn_kernel<<<dim3(L_SEQ / 128, HB), 256, ATTN_SMEM_BYTES>>>(attn_out);

    // band normalize on side stream (needs attn); overlaps FC + LN
    cudaEventRecord(evAttn, 0);
    cudaStreamWaitEvent(s2, evAttn, 0);
    band_norm_kernel<<<HB * L_SEQ, 96, 0, s2>>>(attn_out);

    mma_gemm_kernel<<<dim3(MROWS / 128, DM / 128, 1), 256, GEMM_SMEM_BYTES>>>(
        bq, bk, bv, bfc, 1);
    ln_kernel<<<MROWS, 256>>>(query, gamma, beta, y_out);

    // join side stream back into default stream
    cudaEventRecord(evJoin, s2);
    cudaStreamWaitEvent((cudaStream_t)0, evJoin, 0);
}